// round 4
// baseline (speedup 1.0000x reference)
#include <cuda_runtime.h>
#include <cstdint>

#define DI __device__ __forceinline__

// ---------------- scratch (device globals; no allocation allowed) ----------
__device__ float g_t1[192 * 192];
__device__ float g_C [48 * 128 * 384];
__device__ float g_t2[48 * 128 * 384];
__device__ float g_t3[192 * 768 * 16];
__device__ float g_Mt[3072 * 768];   // M transposed: [n=3072][k=768], tf32-rounded

// ---------------- helpers ---------------------------------------------------
DI float tf32r(float x) {
    uint32_t u;
    asm("cvt.rna.tf32.f32 %0, %1;" : "=r"(u) : "f"(x));
    return __uint_as_float(u);
}

DI void mma_tf32(float c[4], const uint32_t a[4], const uint32_t b[2]) {
    asm("mma.sync.aligned.m16n8k8.row.col.f32.tf32.tf32.f32 "
        "{%0,%1,%2,%3}, {%4,%5,%6,%7}, {%8,%9}, {%0,%1,%2,%3};"
        : "+f"(c[0]), "+f"(c[1]), "+f"(c[2]), "+f"(c[3])
        : "r"(a[0]), "r"(a[1]), "r"(a[2]), "r"(a[3]),
          "r"(b[0]), "r"(b[1]));
}

// ---------------- step 1: t1 = core0 x core1 [192x192] ----------------------
__global__ void k_t1(const float* __restrict__ c0, const float* __restrict__ c1) {
    int idx = blockIdx.x * blockDim.x + threadIdx.x;
    if (idx >= 192 * 192) return;
    int p = idx / 192, q = idx % 192;
    int Ii = p >> 4, Oo = p & 15;
    int I = Ii >> 2, i = Ii & 3, O = Oo >> 2, o = Oo & 3;
    float acc = 0.f;
#pragma unroll
    for (int r = 0; r < 12; ++r)
        acc += c0[(I * 4 + O) * 12 + r] * c1[((r * 4 + i) * 4 + o) * 192 + q];
    g_t1[idx] = acc;
}

// ---------------- mid GEMM (fp32) -------------------------------------------
template <int STEP>
__global__ void gemm_mid(const float* __restrict__ B, int M, int N, int K) {
    const float* __restrict__ A = (STEP == 0) ? g_t1 : g_t2;
    float* __restrict__ C = g_C;
    __shared__ float As[16][68];
    __shared__ float Bs[16][64];
    int tid = threadIdx.x;
    int bm = blockIdx.y * 64, bn = blockIdx.x * 64;
    int row = (tid / 16) * 4, col = (tid % 16) * 4;
    float acc[4][4] = {};
    int arow = tid >> 2, ac = (tid & 3) * 4;
    int brow = tid >> 4, bc = (tid & 15) * 4;
    for (int kt = 0; kt < K; kt += 16) {
        float4 av = *(const float4*)&A[(size_t)(bm + arow) * K + kt + ac];
        float4 bv = *(const float4*)&B[(size_t)(kt + brow) * N + bn + bc];
        __syncthreads();
        As[ac + 0][arow] = av.x; As[ac + 1][arow] = av.y;
        As[ac + 2][arow] = av.z; As[ac + 3][arow] = av.w;
        *(float4*)&Bs[brow][bc] = bv;
        __syncthreads();
#pragma unroll
        for (int kk = 0; kk < 16; ++kk) {
            float4 a = *(const float4*)&As[kk][row];
            float4 b = *(const float4*)&Bs[kk][col];
            float aa[4] = {a.x, a.y, a.z, a.w};
            float bb[4] = {b.x, b.y, b.z, b.w};
#pragma unroll
            for (int ii = 0; ii < 4; ++ii)
#pragma unroll
                for (int jj = 0; jj < 4; ++jj)
                    acc[ii][jj] += aa[ii] * bb[jj];
        }
    }
#pragma unroll
    for (int ii = 0; ii < 4; ++ii)
#pragma unroll
        for (int jj = 0; jj < 4; ++jj)
            C[(size_t)(bm + row + ii) * N + bn + col + jj] = acc[ii][jj];
}

__global__ void k_reidx2() {
    int idx = blockIdx.x * 256 + threadIdx.x;
    int q = idx % 384;
    int t = idx / 384;
    int Oo2 = t % 128, Ii2 = t / 128;
    int Ii = Ii2 >> 2, i = Ii2 & 3, Oo = Oo2 >> 3, o = Oo2 & 7;
    g_t2[idx] = g_C[(size_t)(Ii * 16 + Oo) * 12288 + (i * 8 + o) * 384 + q];
}

__global__ void k_reidx3() {
    int idx = blockIdx.x * 256 + threadIdx.x;
    int q = idx & 15;
    int t = idx >> 4;
    int Oo3 = t % 768, Ii3 = t / 768;
    int Ii2 = Ii3 >> 2, i3 = Ii3 & 3;
    int Oo2 = Oo3 / 6, o3 = Oo3 % 6;
    g_t3[idx] = g_C[(size_t)(Ii2 * 128 + Oo2) * 384 + (i3 * 6 + o3) * 16 + q];
}

// step 4: build M transposed [n][k], tf32-rounded
__global__ void k_t4(const float* __restrict__ c4) {
    __shared__ float Bs[256];
    int tid = threadIdx.x;
    Bs[tid] = c4[tid];
    __syncthreads();
    int p = blockIdx.x * 256 + tid;
    float a[16];
#pragma unroll
    for (int j = 0; j < 4; ++j) {
        float4 v = *(const float4*)&g_t3[(size_t)p * 16 + j * 4];
        a[j * 4 + 0] = v.x; a[j * 4 + 1] = v.y; a[j * 4 + 2] = v.z; a[j * 4 + 3] = v.w;
    }
    int Ii3 = p / 768, Oo3 = p % 768;
#pragma unroll
    for (int n = 0; n < 16; ++n) {
        float acc = 0.f;
#pragma unroll
        for (int q = 0; q < 16; ++q) acc += a[q] * Bs[q * 16 + n];
        int i4 = n >> 2, o4 = n & 3;
        // M row (k) = Ii3*4+i4, M col (n) = Oo3*4+o4; store [n][k]
        g_Mt[(size_t)(Oo3 * 4 + o4) * 768 + (Ii3 * 4 + i4)] = tf32r(acc);
    }
}

// ---------------- main GEMM: Y = X * M + bias, fragment-major SMEM ----------
// BM=128 BN=128 BK=32, 8 warps (2x4), warp tile 64x32, tf32 m16n8k8.
// A smem layout: float4 frag {A[g][tg],A[g+8][tg],A[g][tg+4],A[g+8][tg+4]}
//   at float idx ((m16*4+ks)*32 + (lane^ks))*4 + reg          (16KB)
// B smem layout: float4 {B[tg][cc],B[tg+4][cc],B[tg][cc+8],B[tg+4][cc+8]}
//   at float idx ((ks*8+wn*2+p)*32 + ((tg*8+g)^ks))*4 + q*2+half  (16KB)
__global__ __launch_bounds__(256, 2)
void k_main(const float* __restrict__ X, const float* __restrict__ bias,
            float* __restrict__ Y) {
    __shared__ float As[4096];
    __shared__ float Bs[4096];

    int tid  = threadIdx.x;
    int warp = tid >> 5, lane = tid & 31;
    int wm = warp >> 2, wn = warp & 3;
    int g  = lane >> 2, tg = lane & 3;
    int bl = tg * 8 + g;                       // B lane permutation

    int row0 = blockIdx.y * 128;
    int col0 = blockIdx.x * 128;

    float c[4][4][4] = {};

    // producer mapping: both A and B stream k-contiguous rows of 768
    int prow = tid >> 3;                       // 0..31
    int kq   = tid & 7;                        // k-octet selector
    int kcv  = kq * 4;                         // k0 in 0..28
    int ksP  = kq >> 1;                        // ks of this thread's float4
    int half = kq & 1;                         // 0: tg+0..3, 1: tg+4..7

    // precompute store bases/offsets per r-iter
    int aBase[4], aOff, bBase[4], bOff;
    {
#pragma unroll
        for (int r = 0; r < 4; ++r) {
            int rr = prow + 32 * r;            // row within 128
            // A: m16, g, h
            int m16 = rr >> 4, sub = rr & 15, ga = sub & 7, h = sub >> 3;
            aBase[r] = (m16 * 4 + ksP) * 128 + 0;
            // store per-element offset uses ((ga*4+e)^ksP)*4 + reg
            // stash ga in high bits of aBase? keep separate array:
            aBase[r] |= ga << 20;              // pack ga
            aBase[r] |= h << 26;               // pack h
            // B: wn', nf split
            int wnb = rr >> 5, c5 = rr & 31;
            int nf = c5 >> 3, pp = nf >> 1, qq = nf & 1, gb = c5 & 7;
            bBase[r] = (ksP * 8 + wnb * 2 + pp) * 128;
            bBase[r] |= gb << 20;
            bBase[r] |= qq << 26;
        }
        aOff = 2 * half;                       // reg = h + 2*half
        bOff = half;                           // slot = q*2 + half
    }

    const float* pa = X    + (size_t)(row0 + prow) * 768 + kcv;
    const float* pb = g_Mt + (size_t)(col0 + prow) * 768 + kcv;

    float4 ra[4], rb[4];
#pragma unroll
    for (int r = 0; r < 4; ++r) {
        ra[r] = *(const float4*)(pa + (size_t)(32 * r) * 768);
        rb[r] = *(const float4*)(pb + (size_t)(32 * r) * 768);
    }

    for (int kt = 0; kt < 768; kt += 32) {
        __syncthreads();
#pragma unroll
        for (int r = 0; r < 4; ++r) {
            int ga = (aBase[r] >> 20) & 7, h = (aBase[r] >> 26) & 1;
            int ab = aBase[r] & 0xFFFFF;
            int reg = h + aOff;
            float v[4] = {tf32r(ra[r].x), tf32r(ra[r].y), tf32r(ra[r].z), tf32r(ra[r].w)};
#pragma unroll
            for (int e = 0; e < 4; ++e)
                As[ab + (((ga * 4 + e) ^ ksP) << 2) + reg] = v[e];

            int gb = (bBase[r] >> 20) & 7, qq = (bBase[r] >> 26) & 1;
            int bb = bBase[r] & 0xFFFFF;
            int slot = qq * 2 + bOff;
            float w[4] = {tf32r(rb[r].x), tf32r(rb[r].y), tf32r(rb[r].z), tf32r(rb[r].w)};
#pragma unroll
            for (int e = 0; e < 4; ++e)
                Bs[bb + (((e * 8 + gb) ^ ksP) << 2) + slot] = w[e];
        }
        __syncthreads();

        if (kt + 32 < 768) {
#pragma unroll
            for (int r = 0; r < 4; ++r) {
                ra[r] = *(const float4*)(pa + (size_t)(32 * r) * 768 + kt + 32);
                rb[r] = *(const float4*)(pb + (size_t)(32 * r) * 768 + kt + 32);
            }
        }

#pragma unroll
        for (int ks = 0; ks < 4; ++ks) {
            uint32_t af[4][4], bf[4][2];
#pragma unroll
            for (int mf = 0; mf < 4; ++mf) {
                float4 v = *(const float4*)&As[((wm * 4 + mf) * 4 + ks) * 128 + ((lane ^ ks) << 2)];
                af[mf][0] = __float_as_uint(v.x);
                af[mf][1] = __float_as_uint(v.y);
                af[mf][2] = __float_as_uint(v.z);
                af[mf][3] = __float_as_uint(v.w);
            }
#pragma unroll
            for (int p = 0; p < 2; ++p) {
                float4 v = *(const float4*)&Bs[(ks * 8 + wn * 2 + p) * 128 + ((bl ^ ks) << 2)];
                bf[2 * p + 0][0] = __float_as_uint(v.x);
                bf[2 * p + 0][1] = __float_as_uint(v.y);
                bf[2 * p + 1][0] = __float_as_uint(v.z);
                bf[2 * p + 1][1] = __float_as_uint(v.w);
            }
#pragma unroll
            for (int mf = 0; mf < 4; ++mf)
#pragma unroll
                for (int nf = 0; nf < 4; ++nf)
                    mma_tf32(c[mf][nf], af[mf], bf[nf]);
        }
    }

    // epilogue: add bias, store
#pragma unroll
    for (int nf = 0; nf < 4; ++nf) {
        int cc = col0 + wn * 32 + nf * 8 + tg * 2;
        float b0 = bias[cc], b1 = bias[cc + 1];
#pragma unroll
        for (int mf = 0; mf < 4; ++mf) {
            int r = row0 + wm * 64 + mf * 16 + g;
            float2 v0 = make_float2(c[mf][nf][0] + b0, c[mf][nf][1] + b1);
            float2 v1 = make_float2(c[mf][nf][2] + b0, c[mf][nf][3] + b1);
            *(float2*)&Y[(size_t)r * 3072 + cc]       = v0;
            *(float2*)&Y[(size_t)(r + 8) * 3072 + cc] = v1;
        }
    }
}

// ---------------- launch -----------------------------------------------------
extern "C" void kernel_launch(void* const* d_in, const int* in_sizes, int n_in,
                              void* d_out, int out_size) {
    const float* x    = (const float*)d_in[0];
    const float* c0   = (const float*)d_in[1];
    const float* c1   = (const float*)d_in[2];
    const float* c2   = (const float*)d_in[3];
    const float* c3   = (const float*)d_in[4];
    const float* c4   = (const float*)d_in[5];
    const float* bias = (const float*)d_in[6];
    float* y = (float*)d_out;

    k_t1<<<144, 256>>>(c0, c1);
    {
        dim3 grid(12288 / 64, 192 / 64);
        gemm_mid<0><<<grid, 256>>>(c2, 192, 12288, 192);
    }
    k_reidx2<<<(48 * 128 * 384) / 256, 256>>>();
    {
        dim3 grid(384 / 64, 6144 / 64);
        gemm_mid<1><<<grid, 256>>>(c3, 6144, 384, 384);
    }
    k_reidx3<<<(192 * 768 * 16) / 256, 256>>>();
    k_t4<<<147456 / 256, 256>>>(c4);

    {
        dim3 grid(3072 / 128, 32768 / 128);
        k_main<<<grid, 256>>>(x, bias, y);
    }
}

// round 5
// speedup vs baseline: 1.3305x; 1.3305x over previous
#include <cuda_runtime.h>
#include <cstdint>

#define DI __device__ __forceinline__

// ---------------- scratch (device globals; no allocation allowed) ----------
__device__ float g_t1[192 * 192];
__device__ float g_C [48 * 128 * 384];
__device__ float g_t2[48 * 128 * 384];
__device__ float g_t3[192 * 768 * 16];
__device__ float g_M [768 * 3072];   // [k][n], n-contiguous, tf32-prerounded

// ---------------- helpers ---------------------------------------------------
DI float tf32r(float x) {
    uint32_t u;
    asm("cvt.rna.tf32.f32 %0, %1;" : "=r"(u) : "f"(x));
    return __uint_as_float(u);
}

DI void mma_tf32(float c[4], const uint32_t a[4], const uint32_t b[2]) {
    asm("mma.sync.aligned.m16n8k8.row.col.f32.tf32.tf32.f32 "
        "{%0,%1,%2,%3}, {%4,%5,%6,%7}, {%8,%9}, {%0,%1,%2,%3};"
        : "+f"(c[0]), "+f"(c[1]), "+f"(c[2]), "+f"(c[3])
        : "r"(a[0]), "r"(a[1]), "r"(a[2]), "r"(a[3]),
          "r"(b[0]), "r"(b[1]));
}

// ---------------- step 1: t1 = core0 x core1 [192x192] ----------------------
__global__ void k_t1(const float* __restrict__ c0, const float* __restrict__ c1) {
    int idx = blockIdx.x * blockDim.x + threadIdx.x;
    if (idx >= 192 * 192) return;
    int p = idx / 192, q = idx % 192;
    int Ii = p >> 4, Oo = p & 15;
    int I = Ii >> 2, i = Ii & 3, O = Oo >> 2, o = Oo & 3;
    float acc = 0.f;
#pragma unroll
    for (int r = 0; r < 12; ++r)
        acc += c0[(I * 4 + O) * 12 + r] * c1[((r * 4 + i) * 4 + o) * 192 + q];
    g_t1[idx] = acc;
}

// ---------------- mid GEMM (fp32) -------------------------------------------
template <int STEP>
__global__ void gemm_mid(const float* __restrict__ B, int M, int N, int K) {
    const float* __restrict__ A = (STEP == 0) ? g_t1 : g_t2;
    float* __restrict__ C = g_C;
    __shared__ float As[16][68];
    __shared__ float Bs[16][64];
    int tid = threadIdx.x;
    int bm = blockIdx.y * 64, bn = blockIdx.x * 64;
    int row = (tid / 16) * 4, col = (tid % 16) * 4;
    float acc[4][4] = {};
    int arow = tid >> 2, ac = (tid & 3) * 4;
    int brow = tid >> 4, bc = (tid & 15) * 4;
    for (int kt = 0; kt < K; kt += 16) {
        float4 av = *(const float4*)&A[(size_t)(bm + arow) * K + kt + ac];
        float4 bv = *(const float4*)&B[(size_t)(kt + brow) * N + bn + bc];
        __syncthreads();
        As[ac + 0][arow] = av.x; As[ac + 1][arow] = av.y;
        As[ac + 2][arow] = av.z; As[ac + 3][arow] = av.w;
        *(float4*)&Bs[brow][bc] = bv;
        __syncthreads();
#pragma unroll
        for (int kk = 0; kk < 16; ++kk) {
            float4 a = *(const float4*)&As[kk][row];
            float4 b = *(const float4*)&Bs[kk][col];
            float aa[4] = {a.x, a.y, a.z, a.w};
            float bb[4] = {b.x, b.y, b.z, b.w};
#pragma unroll
            for (int ii = 0; ii < 4; ++ii)
#pragma unroll
                for (int jj = 0; jj < 4; ++jj)
                    acc[ii][jj] += aa[ii] * bb[jj];
        }
    }
#pragma unroll
    for (int ii = 0; ii < 4; ++ii)
#pragma unroll
        for (int jj = 0; jj < 4; ++jj)
            C[(size_t)(bm + row + ii) * N + bn + col + jj] = acc[ii][jj];
}

__global__ void k_reidx2() {
    int idx = blockIdx.x * 256 + threadIdx.x;
    int q = idx % 384;
    int t = idx / 384;
    int Oo2 = t % 128, Ii2 = t / 128;
    int Ii = Ii2 >> 2, i = Ii2 & 3, Oo = Oo2 >> 3, o = Oo2 & 7;
    g_t2[idx] = g_C[(size_t)(Ii * 16 + Oo) * 12288 + (i * 8 + o) * 384 + q];
}

__global__ void k_reidx3() {
    int idx = blockIdx.x * 256 + threadIdx.x;
    int q = idx & 15;
    int t = idx >> 4;
    int Oo3 = t % 768, Ii3 = t / 768;
    int Ii2 = Ii3 >> 2, i3 = Ii3 & 3;
    int Oo2 = Oo3 / 6, o3 = Oo3 % 6;
    g_t3[idx] = g_C[(size_t)(Ii2 * 128 + Oo2) * 384 + (i3 * 6 + o3) * 16 + q];
}

// step 4: M[k][n], tf32-prerounded
__global__ void k_t4(const float* __restrict__ c4) {
    __shared__ float Bs[256];
    int tid = threadIdx.x;
    Bs[tid] = c4[tid];
    __syncthreads();
    int p = blockIdx.x * 256 + tid;
    float a[16];
#pragma unroll
    for (int j = 0; j < 4; ++j) {
        float4 v = *(const float4*)&g_t3[(size_t)p * 16 + j * 4];
        a[j * 4 + 0] = v.x; a[j * 4 + 1] = v.y; a[j * 4 + 2] = v.z; a[j * 4 + 3] = v.w;
    }
    int Ii3 = p / 768, Oo3 = p % 768;
#pragma unroll
    for (int n = 0; n < 16; ++n) {
        float acc = 0.f;
#pragma unroll
        for (int q = 0; q < 16; ++q) acc += a[q] * Bs[q * 16 + n];
        int i4 = n >> 2, o4 = n & 3;
        g_M[(size_t)(Ii3 * 4 + i4) * 3072 + Oo3 * 4 + o4] = tf32r(acc);
    }
}

// ---------------- main GEMM: Y = X * M + bias -------------------------------
// BM=128, BN=256, BK=32, 8 warps (2x4), warp tile 64x64, tf32 m16n8k8.
// Double-buffered smem, one barrier per K-tile.
// As stride 36 (frag banks 4g+tg: conflict-free), Bs stride 264 (8tg+g: c-free).
static constexpr int AS_STRIDE = 36;
static constexpr int BS_STRIDE = 264;
static constexpr int AS_FLOATS = 128 * AS_STRIDE;      // 4608
static constexpr int BS_FLOATS = 32 * BS_STRIDE;       // 8448
static constexpr int SMEM_MAIN = (2 * AS_FLOATS + 2 * BS_FLOATS) * 4;  // 104448 B

__global__ __launch_bounds__(256, 1)
void k_main(const float* __restrict__ X, const float* __restrict__ bias,
            float* __restrict__ Y) {
    extern __shared__ float smem[];
    float* As[2] = { smem, smem + AS_FLOATS };
    float* Bs[2] = { smem + 2 * AS_FLOATS, smem + 2 * AS_FLOATS + BS_FLOATS };

    int tid  = threadIdx.x;
    int warp = tid >> 5, lane = tid & 31;
    int wm = warp >> 2, wn = warp & 3;
    int g  = lane >> 2, tg = lane & 3;

    int col0 = blockIdx.x * 256;
    int row0 = blockIdx.y * 128;

    float c[4][8][4] = {};

    // producer mapping
    int arow = tid >> 3;               // 0..31 (A rows, +32r)
    int acv  = (tid & 7) * 4;          // A k-offset
    int brow = tid >> 6;               // 0..3  (B k-rows, +4r)
    int bcv  = (tid & 63) * 4;         // B n-offset

    const float* pa = X   + (size_t)(row0 + arow) * 768 + acv;
    const float* pb = g_M + (size_t)brow * 3072 + col0 + bcv;

    float4 ra[4], rb[8];
#pragma unroll
    for (int r = 0; r < 4; ++r) ra[r] = *(const float4*)(pa + (size_t)(32 * r) * 768);
#pragma unroll
    for (int r = 0; r < 8; ++r) rb[r] = *(const float4*)(pb + (size_t)(4 * r) * 3072);

    // prologue: fill buf 0
#pragma unroll
    for (int r = 0; r < 4; ++r) {
        float4 v = ra[r];
        *(float4*)&As[0][(arow + 32 * r) * AS_STRIDE + acv] =
            make_float4(tf32r(v.x), tf32r(v.y), tf32r(v.z), tf32r(v.w));
    }
#pragma unroll
    for (int r = 0; r < 8; ++r) {
        float4 v = rb[r];
        *(float4*)&Bs[0][(brow + 4 * r) * BS_STRIDE + bcv] =
            make_float4(tf32r(v.x), tf32r(v.y), tf32r(v.z), tf32r(v.w));
    }
    __syncthreads();

    int buf = 0;
    for (int t = 0; t < 24; ++t) {
        // issue LDGs for next tile early
        if (t < 23) {
            int kt = (t + 1) * 32;
#pragma unroll
            for (int r = 0; r < 4; ++r)
                ra[r] = *(const float4*)(pa + (size_t)(32 * r) * 768 + kt);
#pragma unroll
            for (int r = 0; r < 8; ++r)
                rb[r] = *(const float4*)(pb + (size_t)(4 * r + kt) * 3072);
        }

        const float* A = As[buf];
        const float* B = Bs[buf];

#pragma unroll
        for (int ks = 0; ks < 4; ++ks) {
            int k = ks * 8;
            uint32_t af[4][4], bf[8][2];
#pragma unroll
            for (int mf = 0; mf < 4; ++mf) {
                int r = (wm * 64 + mf * 16 + g) * AS_STRIDE + k + tg;
                af[mf][0] = __float_as_uint(A[r]);
                af[mf][1] = __float_as_uint(A[r + 8 * AS_STRIDE]);
                af[mf][2] = __float_as_uint(A[r + 4]);
                af[mf][3] = __float_as_uint(A[r + 8 * AS_STRIDE + 4]);
            }
#pragma unroll
            for (int nf = 0; nf < 8; ++nf) {
                int cc = wn * 64 + nf * 8 + g;
                bf[nf][0] = __float_as_uint(B[(k + tg) * BS_STRIDE + cc]);
                bf[nf][1] = __float_as_uint(B[(k + tg + 4) * BS_STRIDE + cc]);
            }
#pragma unroll
            for (int mf = 0; mf < 4; ++mf)
#pragma unroll
                for (int nf = 0; nf < 8; ++nf)
                    mma_tf32(c[mf][nf], af[mf], bf[nf]);

            // interleave next-tile STS after 2 ks blocks (LDG latency covered)
            if (ks == 1 && t < 23) {
                float* An = As[buf ^ 1];
                float* Bn = Bs[buf ^ 1];
#pragma unroll
                for (int r = 0; r < 4; ++r) {
                    float4 v = ra[r];
                    *(float4*)&An[(arow + 32 * r) * AS_STRIDE + acv] =
                        make_float4(tf32r(v.x), tf32r(v.y), tf32r(v.z), tf32r(v.w));
                }
#pragma unroll
                for (int r = 0; r < 8; ++r) {
                    float4 v = rb[r];
                    *(float4*)&Bn[(brow + 4 * r) * BS_STRIDE + bcv] =
                        make_float4(tf32r(v.x), tf32r(v.y), tf32r(v.z), tf32r(v.w));
                }
            }
        }
        __syncthreads();
        buf ^= 1;
    }

    // epilogue: add bias, store
#pragma unroll
    for (int nf = 0; nf < 8; ++nf) {
        int cc = col0 + wn * 64 + nf * 8 + tg * 2;
        float b0 = bias[cc], b1 = bias[cc + 1];
#pragma unroll
        for (int mf = 0; mf < 4; ++mf) {
            int r = row0 + wm * 64 + mf * 16 + g;
            float2 v0 = make_float2(c[mf][nf][0] + b0, c[mf][nf][1] + b1);
            float2 v1 = make_float2(c[mf][nf][2] + b0, c[mf][nf][3] + b1);
            *(float2*)&Y[(size_t)r * 3072 + cc]       = v0;
            *(float2*)&Y[(size_t)(r + 8) * 3072 + cc] = v1;
        }
    }
}

// ---------------- launch -----------------------------------------------------
extern "C" void kernel_launch(void* const* d_in, const int* in_sizes, int n_in,
                              void* d_out, int out_size) {
    const float* x    = (const float*)d_in[0];
    const float* c0   = (const float*)d_in[1];
    const float* c1   = (const float*)d_in[2];
    const float* c2   = (const float*)d_in[3];
    const float* c3   = (const float*)d_in[4];
    const float* c4   = (const float*)d_in[5];
    const float* bias = (const float*)d_in[6];
    float* y = (float*)d_out;

    k_t1<<<144, 256>>>(c0, c1);
    {
        dim3 grid(12288 / 64, 192 / 64);
        gemm_mid<0><<<grid, 256>>>(c2, 192, 12288, 192);
    }
    k_reidx2<<<(48 * 128 * 384) / 256, 256>>>();
    {
        dim3 grid(384 / 64, 6144 / 64);
        gemm_mid<1><<<grid, 256>>>(c3, 6144, 384, 384);
    }
    k_reidx3<<<(192 * 768 * 16) / 256, 256>>>();
    k_t4<<<147456 / 256, 256>>>(c4);

    cudaFuncSetAttribute(k_main, cudaFuncAttributeMaxDynamicSharedMemorySize, SMEM_MAIN);
    {
        dim3 grid(3072 / 256, 32768 / 128);
        k_main<<<grid, 256, SMEM_MAIN>>>(x, bias, y);
    }
}

// round 6
// speedup vs baseline: 1.6229x; 1.2198x over previous
#include <cuda_runtime.h>
#include <cstdint>

#define DI __device__ __forceinline__

// ---------------- scratch (device globals; no allocation allowed) ----------
__device__ float g_t1[192 * 192];
__device__ float g_C [48 * 128 * 384];
__device__ float g_t2[48 * 128 * 384];
__device__ float g_t3[192 * 768 * 16];
__device__ float g_M [768 * 3072];   // [k][n], n-contiguous, tf32-prerounded

// ---------------- helpers ---------------------------------------------------
DI float tf32r(float x) {
    uint32_t u;
    asm("cvt.rna.tf32.f32 %0, %1;" : "=r"(u) : "f"(x));
    return __uint_as_float(u);
}
DI uint32_t smem_u32(const void* p) {
    uint32_t a;
    asm("{ .reg .u64 t; cvta.to.shared.u64 t, %1; cvt.u32.u64 %0, t; }" : "=r"(a) : "l"(p));
    return a;
}
DI void mma_tf32(float c[4], const uint32_t a[4], const uint32_t b[2]) {
    asm("mma.sync.aligned.m16n8k8.row.col.f32.tf32.tf32.f32 "
        "{%0,%1,%2,%3}, {%4,%5,%6,%7}, {%8,%9}, {%0,%1,%2,%3};"
        : "+f"(c[0]), "+f"(c[1]), "+f"(c[2]), "+f"(c[3])
        : "r"(a[0]), "r"(a[1]), "r"(a[2]), "r"(a[3]),
          "r"(b[0]), "r"(b[1]));
}
#define CP16(d, s)  asm volatile("cp.async.cg.shared.global [%0], [%1], 16;" :: "r"(d), "l"(s) : "memory")
#define CP_COMMIT() asm volatile("cp.async.commit_group;" ::: "memory")
#define CP_WAIT2()  asm volatile("cp.async.wait_group 2;" ::: "memory")

// ---------------- step 1: t1 = core0 x core1 [192x192] ----------------------
__global__ void k_t1(const float* __restrict__ c0, const float* __restrict__ c1) {
    int idx = blockIdx.x * blockDim.x + threadIdx.x;
    if (idx >= 192 * 192) return;
    int p = idx / 192, q = idx % 192;
    int Ii = p >> 4, Oo = p & 15;
    int I = Ii >> 2, i = Ii & 3, O = Oo >> 2, o = Oo & 3;
    float acc = 0.f;
#pragma unroll
    for (int r = 0; r < 12; ++r)
        acc += c0[(I * 4 + O) * 12 + r] * c1[((r * 4 + i) * 4 + o) * 192 + q];
    g_t1[idx] = acc;
}

// ---------------- mid GEMM (fp32) -------------------------------------------
template <int STEP>
__global__ void gemm_mid(const float* __restrict__ B, int M, int N, int K) {
    const float* __restrict__ A = (STEP == 0) ? g_t1 : g_t2;
    float* __restrict__ C = g_C;
    __shared__ float As[16][68];
    __shared__ float Bs[16][64];
    int tid = threadIdx.x;
    int bm = blockIdx.y * 64, bn = blockIdx.x * 64;
    int row = (tid / 16) * 4, col = (tid % 16) * 4;
    float acc[4][4] = {};
    int arow = tid >> 2, ac = (tid & 3) * 4;
    int brow = tid >> 4, bc = (tid & 15) * 4;
    for (int kt = 0; kt < K; kt += 16) {
        float4 av = *(const float4*)&A[(size_t)(bm + arow) * K + kt + ac];
        float4 bv = *(const float4*)&B[(size_t)(kt + brow) * N + bn + bc];
        __syncthreads();
        As[ac + 0][arow] = av.x; As[ac + 1][arow] = av.y;
        As[ac + 2][arow] = av.z; As[ac + 3][arow] = av.w;
        *(float4*)&Bs[brow][bc] = bv;
        __syncthreads();
#pragma unroll
        for (int kk = 0; kk < 16; ++kk) {
            float4 a = *(const float4*)&As[kk][row];
            float4 b = *(const float4*)&Bs[kk][col];
            float aa[4] = {a.x, a.y, a.z, a.w};
            float bb[4] = {b.x, b.y, b.z, b.w};
#pragma unroll
            for (int ii = 0; ii < 4; ++ii)
#pragma unroll
                for (int jj = 0; jj < 4; ++jj)
                    acc[ii][jj] += aa[ii] * bb[jj];
        }
    }
#pragma unroll
    for (int ii = 0; ii < 4; ++ii)
#pragma unroll
        for (int jj = 0; jj < 4; ++jj)
            C[(size_t)(bm + row + ii) * N + bn + col + jj] = acc[ii][jj];
}

__global__ void k_reidx2() {
    int idx = blockIdx.x * 256 + threadIdx.x;
    int q = idx % 384;
    int t = idx / 384;
    int Oo2 = t % 128, Ii2 = t / 128;
    int Ii = Ii2 >> 2, i = Ii2 & 3, Oo = Oo2 >> 3, o = Oo2 & 7;
    g_t2[idx] = g_C[(size_t)(Ii * 16 + Oo) * 12288 + (i * 8 + o) * 384 + q];
}

__global__ void k_reidx3() {
    int idx = blockIdx.x * 256 + threadIdx.x;
    int q = idx & 15;
    int t = idx >> 4;
    int Oo3 = t % 768, Ii3 = t / 768;
    int Ii2 = Ii3 >> 2, i3 = Ii3 & 3;
    int Oo2 = Oo3 / 6, o3 = Oo3 % 6;
    g_t3[idx] = g_C[(size_t)(Ii2 * 128 + Oo2) * 384 + (i3 * 6 + o3) * 16 + q];
}

// step 4: M[k][n], tf32-prerounded
__global__ void k_t4(const float* __restrict__ c4) {
    __shared__ float Bs[256];
    int tid = threadIdx.x;
    Bs[tid] = c4[tid];
    __syncthreads();
    int p = blockIdx.x * 256 + tid;
    float a[16];
#pragma unroll
    for (int j = 0; j < 4; ++j) {
        float4 v = *(const float4*)&g_t3[(size_t)p * 16 + j * 4];
        a[j * 4 + 0] = v.x; a[j * 4 + 1] = v.y; a[j * 4 + 2] = v.z; a[j * 4 + 3] = v.w;
    }
    int Ii3 = p / 768, Oo3 = p % 768;
#pragma unroll
    for (int n = 0; n < 16; ++n) {
        float acc = 0.f;
#pragma unroll
        for (int q = 0; q < 16; ++q) acc += a[q] * Bs[q * 16 + n];
        int i4 = n >> 2, o4 = n & 3;
        g_M[(size_t)(Ii3 * 4 + i4) * 3072 + Oo3 * 4 + o4] = tf32r(acc);
    }
}

// ---------------- main GEMM: Y = X * M + bias -------------------------------
// BM=128, BN=256, BK=32; 8 warps (2x4), warp tile 64x64; tf32 m16n8k8.
// cp.async.cg 4-stage pipeline; A cvt->tf32 at fragment load; B pre-rounded.
// A smem stride 36 floats (frag banks 4g+tg), B stride 264 (banks 8tg+g).
static constexpr int A_STRIDE_B = 36 * 4;        // 144 B per A row
static constexpr int B_STRIDE_B = 264 * 4;       // 1056 B per B row
static constexpr int A_STAGE   = 128 * A_STRIDE_B;   // 18432
static constexpr int B_STAGE   = 32 * B_STRIDE_B;    // 33792
static constexpr int STAGE     = A_STAGE + B_STAGE;  // 52224
static constexpr int NSTAGE    = 4;
static constexpr int SMEM_MAIN = NSTAGE * STAGE;     // 208896

__global__ __launch_bounds__(256, 1)
void k_main(const float* __restrict__ X, const float* __restrict__ bias,
            float* __restrict__ Y) {
    extern __shared__ char smem[];
    uint32_t sb = smem_u32(smem);

    int tid  = threadIdx.x;
    int warp = tid >> 5, lane = tid & 31;
    int wm = warp >> 2, wn = warp & 3;            // 2 x 4 warp grid
    int g  = lane >> 2, tg = lane & 3;

    int col0 = blockIdx.x * 256;
    int row0 = blockIdx.y * 128;

    float c[4][8][4] = {};

    // ---- cp.async per-thread mapping ----
    // A: 1024 16B-chunks/tile; thread does 4 (rows tid>>3 + 32i, col-octet tid&7)
    // B: 2048 16B-chunks/tile; thread does 8 (rows tid>>6 + 4i, n-chunk tid&63)
    const float* aS0 = X + (size_t)(row0 + (tid >> 3)) * 768 + (tid & 7) * 4;
    const float* bS0 = g_M + (size_t)(tid >> 6) * 3072 + col0 + (tid & 63) * 4;
    uint32_t aD0 = (uint32_t)((tid >> 3) * A_STRIDE_B + (tid & 7) * 16);
    uint32_t bD0 = (uint32_t)((tid >> 6) * B_STRIDE_B + (tid & 63) * 16);

    // prologue: issue stages 0..2 (tiles 0..2)
#pragma unroll
    for (int t = 0; t < 3; ++t) {
        uint32_t base = sb + t * STAGE;
#pragma unroll
        for (int i = 0; i < 4; ++i)
            CP16(base + aD0 + i * (32 * A_STRIDE_B), aS0 + (size_t)i * 32 * 768 + t * 32);
#pragma unroll
        for (int i = 0; i < 8; ++i)
            CP16(base + A_STAGE + bD0 + i * (4 * B_STRIDE_B), bS0 + (size_t)(i * 4 + t * 32) * 3072);
        CP_COMMIT();
    }

    for (int t = 0; t < 24; ++t) {
        CP_WAIT2();
        __syncthreads();

        // issue tile t+3 into stage (t+3)&3 == (t-1)&3, freed by last iter's reads
        if (t + 3 < 24) {
            int tn = t + 3;
            uint32_t base = sb + (tn & 3) * STAGE;
#pragma unroll
            for (int i = 0; i < 4; ++i)
                CP16(base + aD0 + i * (32 * A_STRIDE_B), aS0 + (size_t)i * 32 * 768 + tn * 32);
#pragma unroll
            for (int i = 0; i < 8; ++i)
                CP16(base + A_STAGE + bD0 + i * (4 * B_STRIDE_B), bS0 + (size_t)(i * 4 + tn * 32) * 3072);
        }
        CP_COMMIT();   // always commit (empty groups keep wait_group invariant)

        const float* A = (const float*)(smem + (t & 3) * STAGE);
        const float* B = (const float*)(smem + (t & 3) * STAGE + A_STAGE);

#pragma unroll
        for (int ks = 0; ks < 4; ++ks) {
            int k = ks * 8;
            uint32_t af[4][4], bf[8][2];
#pragma unroll
            for (int mf = 0; mf < 4; ++mf) {
                int r = (wm * 64 + mf * 16 + g) * 36 + k + tg;
                af[mf][0] = __float_as_uint(tf32r(A[r]));
                af[mf][1] = __float_as_uint(tf32r(A[r + 8 * 36]));
                af[mf][2] = __float_as_uint(tf32r(A[r + 4]));
                af[mf][3] = __float_as_uint(tf32r(A[r + 8 * 36 + 4]));
            }
#pragma unroll
            for (int nf = 0; nf < 8; ++nf) {
                int cc = (k + tg) * 264 + wn * 64 + nf * 8 + g;
                bf[nf][0] = __float_as_uint(B[cc]);
                bf[nf][1] = __float_as_uint(B[cc + 4 * 264]);
            }
#pragma unroll
            for (int mf = 0; mf < 4; ++mf)
#pragma unroll
                for (int nf = 0; nf < 8; ++nf)
                    mma_tf32(c[mf][nf], af[mf], bf[nf]);
        }
        __syncthreads();   // all reads of stage t done before reuse
    }

    // epilogue: add bias, store
#pragma unroll
    for (int nf = 0; nf < 8; ++nf) {
        int cc = col0 + wn * 64 + nf * 8 + tg * 2;
        float b0 = bias[cc], b1 = bias[cc + 1];
#pragma unroll
        for (int mf = 0; mf < 4; ++mf) {
            int r = row0 + wm * 64 + mf * 16 + g;
            float2 v0 = make_float2(c[mf][nf][0] + b0, c[mf][nf][1] + b1);
            float2 v1 = make_float2(c[mf][nf][2] + b0, c[mf][nf][3] + b1);
            *(float2*)&Y[(size_t)r * 3072 + cc]       = v0;
            *(float2*)&Y[(size_t)(r + 8) * 3072 + cc] = v1;
        }
    }
}

// ---------------- launch -----------------------------------------------------
extern "C" void kernel_launch(void* const* d_in, const int* in_sizes, int n_in,
                              void* d_out, int out_size) {
    const float* x    = (const float*)d_in[0];
    const float* c0   = (const float*)d_in[1];
    const float* c1   = (const float*)d_in[2];
    const float* c2   = (const float*)d_in[3];
    const float* c3   = (const float*)d_in[4];
    const float* c4   = (const float*)d_in[5];
    const float* bias = (const float*)d_in[6];
    float* y = (float*)d_out;

    k_t1<<<144, 256>>>(c0, c1);
    {
        dim3 grid(12288 / 64, 192 / 64);
        gemm_mid<0><<<grid, 256>>>(c2, 192, 12288, 192);
    }
    k_reidx2<<<(48 * 128 * 384) / 256, 256>>>();
    {
        dim3 grid(384 / 64, 6144 / 64);
        gemm_mid<1><<<grid, 256>>>(c3, 6144, 384, 384);
    }
    k_reidx3<<<(192 * 768 * 16) / 256, 256>>>();
    k_t4<<<147456 / 256, 256>>>(c4);

    cudaFuncSetAttribute(k_main, cudaFuncAttributeMaxDynamicSharedMemorySize, SMEM_MAIN);
    {
        dim3 grid(3072 / 256, 32768 / 128);
        k_main<<<grid, 256, SMEM_MAIN>>>(x, bias, y);
    }
}